// round 1
// baseline (speedup 1.0000x reference)
#include <cuda_runtime.h>
#include <math.h>

#define N_NODES 50000
#define N_EDGES 800000
#define NHEADS  8
#define MULT    16

// Scratch: exp(scores) per (edge, head) and softmax denominators per (node, head).
__device__ float g_e[(size_t)N_EDGES * NHEADS];   // 25.6 MB
__device__ float g_s[(size_t)N_NODES * NHEADS];   // 1.6 MB (holds sum, then inverted)

// ---------------------------------------------------------------------------
// Pass 1: one thread per (edge, head).
//   dot = <k[e,h,:], q[col[e],h,:]> over 8 feats (2 from k0/q0, 6 from k1/q1)
//   w   = exp(dot / 8);  g_e[e*8+h] = w;  atomicAdd(g_s[row*8+h], w)
// k/q reads are fully coalesced (8 consecutive threads cover one edge's
// contiguous 64 floats). q gathers hit L2 (q is 12.8 MB, L2-resident).
// ---------------------------------------------------------------------------
__global__ void __launch_bounds__(256) pass1_scores(
    const float* __restrict__ k0, const float* __restrict__ k1,
    const float* __restrict__ q0, const float* __restrict__ q1,
    const int* __restrict__ row_idx, const int* __restrict__ col_idx)
{
    int t = blockIdx.x * blockDim.x + threadIdx.x;
    if (t >= N_EDGES * NHEADS) return;
    int e = t >> 3;
    int h = t & 7;

    int col = __ldg(col_idx + e);

    const float2* k0p = (const float2*)(k0 + (size_t)e   * 16 + 2 * h);
    const float2* q0p = (const float2*)(q0 + (size_t)col * 16 + 2 * h);
    float2 ka = *k0p;
    float2 qa = *q0p;
    float dot = ka.x * qa.x + ka.y * qa.y;

    const float2* k1p = (const float2*)(k1 + (size_t)e   * 48 + 6 * h);
    const float2* q1p = (const float2*)(q1 + (size_t)col * 48 + 6 * h);
#pragma unroll
    for (int j = 0; j < 3; j++) {
        float2 kb = k1p[j];
        float2 qb = q1p[j];
        dot += kb.x * qb.x + kb.y * qb.y;
    }

    float w = expf(dot * 0.125f);   // 1/sqrt(F_KEY_NFEAT=64)
    g_e[t] = w;

    int rw = __ldg(row_idx + e);
    atomicAdd(&g_s[rw * NHEADS + h], w);
}

// ---------------------------------------------------------------------------
// Pass 1.5: invert denominators once so pass 2 multiplies instead of divides.
// ---------------------------------------------------------------------------
__global__ void __launch_bounds__(256) invert_s()
{
    int t = blockIdx.x * blockDim.x + threadIdx.x;
    if (t >= N_NODES * NHEADS) return;
    float s = g_s[t];
    g_s[t] = (s > 0.0f) ? (1.0f / s) : 0.0f;
}

// ---------------------------------------------------------------------------
// Pass 2: one thread per (edge, 16B-output-chunk). 16 threads per edge.
// The 64 output floats of an edge are:
//   out0[col, g]   (g = 0..15):  a[g/2] * v0[e, g]
//   out1[col, f]   (f = 0..47):  a[f/6] * v1[e, f]     (flat over (mult, 3))
// where a[h] = g_e[e*8+h] * g_s_inv[row*8+h].
// Each thread emits ONE red.global.add.v4.f32 — 16 vector atomics per edge
// instead of 64 scalar atomicAdds.
// ---------------------------------------------------------------------------
__global__ void __launch_bounds__(256) pass2_scatter(
    const float* __restrict__ v0, const float* __restrict__ v1,
    const int* __restrict__ row_idx, const int* __restrict__ col_idx,
    float* __restrict__ out0, float* __restrict__ out1)
{
    int t = blockIdx.x * blockDim.x + threadIdx.x;
    if (t >= N_EDGES * 16) return;
    int e = t >> 4;
    int j = t & 15;

    int rw  = __ldg(row_idx + e);
    int col = __ldg(col_idx + e);

    const float* eb = g_e + (size_t)e  * NHEADS;
    const float* sb = g_s + (size_t)rw * NHEADS;

    float4 o;
    float* p;
    if (j < 4) {
        // out0 chunk: floats g = 4j .. 4j+3, head = g>>1 -> {2j, 2j+1}
        float4 v = *(const float4*)(v0 + (size_t)e * 16 + 4 * j);
        float a0 = eb[2 * j]     * sb[2 * j];
        float a1 = eb[2 * j + 1] * sb[2 * j + 1];
        o = make_float4(v.x * a0, v.y * a0, v.z * a1, v.w * a1);
        p = out0 + (size_t)col * 16 + 4 * j;
    } else {
        // out1 chunk: floats f = f0 .. f0+3, head = f/6 (at most 2 distinct)
        int f0 = 4 * (j - 4);
        float4 v = *(const float4*)(v1 + (size_t)e * 48 + f0);
        int ha = f0 / 6;
        int hb = (f0 + 3) / 6;
        float alo = eb[ha] * sb[ha];
        float ahi = (hb == ha) ? alo : eb[hb] * sb[hb];
        float a0 = ((f0 + 0) / 6 == ha) ? alo : ahi;
        float a1 = ((f0 + 1) / 6 == ha) ? alo : ahi;
        float a2 = ((f0 + 2) / 6 == ha) ? alo : ahi;
        float a3 = ((f0 + 3) / 6 == ha) ? alo : ahi;
        o = make_float4(v.x * a0, v.y * a1, v.z * a2, v.w * a3);
        p = out1 + (size_t)col * 48 + f0;
    }

    asm volatile("red.global.add.v4.f32 [%0], {%1, %2, %3, %4};"
                 :: "l"(p), "f"(o.x), "f"(o.y), "f"(o.z), "f"(o.w)
                 : "memory");
}

// ---------------------------------------------------------------------------
// Launch
// Inputs (metadata order): v0, v1, k0, k1, q0, q1, edge_index
// Output: out0 (N*16 floats) followed by out1 (N*48 floats)
// ---------------------------------------------------------------------------
extern "C" void kernel_launch(void* const* d_in, const int* in_sizes, int n_in,
                              void* d_out, int out_size)
{
    const float* v0 = (const float*)d_in[0];
    const float* v1 = (const float*)d_in[1];
    const float* k0 = (const float*)d_in[2];
    const float* k1 = (const float*)d_in[3];
    const float* q0 = (const float*)d_in[4];
    const float* q1 = (const float*)d_in[5];
    const int*   ei = (const int*)  d_in[6];
    const int* row_idx = ei;             // edge_index[0]
    const int* col_idx = ei + N_EDGES;   // edge_index[1]

    float* out0 = (float*)d_out;
    float* out1 = out0 + (size_t)N_NODES * MULT;

    void* s_addr = nullptr;
    cudaGetSymbolAddress(&s_addr, g_s);

    cudaMemsetAsync(s_addr, 0, (size_t)N_NODES * NHEADS * sizeof(float));
    cudaMemsetAsync(d_out, 0, (size_t)out_size * sizeof(float));

    int n1 = N_EDGES * NHEADS;
    pass1_scores<<<(n1 + 255) / 256, 256>>>(k0, k1, q0, q1, row_idx, col_idx);

    int ns = N_NODES * NHEADS;
    invert_s<<<(ns + 255) / 256, 256>>>();

    int n2 = N_EDGES * 16;
    pass2_scatter<<<(n2 + 255) / 256, 256>>>(v0, v1, row_idx, col_idx, out0, out1);
}